// round 11
// baseline (speedup 1.0000x reference)
#include <cuda_runtime.h>

// Stochastic-LIF eval-mode scan.
// x: [B=32, T=128, N=8192] f32, o: same shape.
// Recurrence per (b, n): u = 0.5*u + x_t; o = (u > 1); u = o ? 0 : u.
//
// Each thread owns one float8 (8 adjacent n, 32 B) across all 128 steps.
// T processed in chunks of 8; the 8 independent 256-bit loads per chunk
// are issued via asm volatile (ld.global.v8.b32, sm_103a) so ptxas cannot
// sink them — true MLP=8 x 32B = 256 B in flight per thread.
// Stores are 2x STG.128 .cs (no 256-bit store path).
// 32768 threads as 512 blocks x 64: ~6.9 warps/SM, ~56 KB in flight/SM.

static constexpr int B = 32;
static constexpr int T = 128;
static constexpr int N = 8192;
static constexpr int NV8 = N / 8;          // float8 columns per (b,t) row: 1024
static constexpr int CHAINS = B * NV8;     // 32768 threads
static constexpr int CH = 8;               // time-chunk (prefetch depth)

__global__ void __launch_bounds__(64)
lif_scan_kernel(const float* __restrict__ x, float* __restrict__ o) {
    const int idx = blockIdx.x * blockDim.x + threadIdx.x;   // 0 .. CHAINS-1
    const int b = idx >> 10;           // / NV8
    const int n = idx & (NV8 - 1);     // % NV8

    // byte strides: one (b,t) row = N floats; thread's column offset = n*8 floats
    const float* __restrict__ xp = x + (size_t)b * T * N + (size_t)n * 8;
    float* __restrict__ op       = o + (size_t)b * T * N + (size_t)n * 8;

    float u[8];
    #pragma unroll
    for (int j = 0; j < 8; ++j) u[j] = 0.f;

    #pragma unroll 1
    for (int t0 = 0; t0 < T; t0 += CH) {
        // Phase 1: 8 independent 256-bit loads, order-pinned by asm volatile.
        unsigned xr[CH][8];
        #pragma unroll
        for (int i = 0; i < CH; ++i) {
            const float* p = xp + (size_t)(t0 + i) * N;
            asm volatile(
                "ld.global.v8.b32 {%0,%1,%2,%3,%4,%5,%6,%7}, [%8];"
                : "=r"(xr[i][0]), "=r"(xr[i][1]), "=r"(xr[i][2]), "=r"(xr[i][3]),
                  "=r"(xr[i][4]), "=r"(xr[i][5]), "=r"(xr[i][6]), "=r"(xr[i][7])
                : "l"(p));
        }

        // Phase 2: sequential LIF chain; 2x streaming STG.128 per step.
        #pragma unroll
        for (int i = 0; i < CH; ++i) {
            float ov[8];
            #pragma unroll
            for (int j = 0; j < 8; ++j) {
                u[j] = fmaf(0.5f, u[j], __uint_as_float(xr[i][j]));
                ov[j] = (u[j] > 1.0f) ? 1.0f : 0.0f;
                u[j]  = (u[j] > 1.0f) ? 0.0f : u[j];
            }

            float* q = op + (size_t)(t0 + i) * N;
            asm volatile("st.global.cs.v4.f32 [%0], {%1,%2,%3,%4};"
                         :: "l"(q), "f"(ov[0]), "f"(ov[1]), "f"(ov[2]), "f"(ov[3])
                         : "memory");
            asm volatile("st.global.cs.v4.f32 [%0], {%1,%2,%3,%4};"
                         :: "l"(q + 4), "f"(ov[4]), "f"(ov[5]), "f"(ov[6]), "f"(ov[7])
                         : "memory");
        }
    }
}

extern "C" void kernel_launch(void* const* d_in, const int* in_sizes, int n_in,
                              void* d_out, int out_size) {
    const float* x = (const float*)d_in[0];
    float* o = (float*)d_out;
    (void)in_sizes; (void)n_in; (void)out_size;

    const int threads = 64;
    const int blocks = CHAINS / threads;   // 512
    lif_scan_kernel<<<blocks, threads>>>(x, o);
}

// round 12
// speedup vs baseline: 1.0667x; 1.0667x over previous
#include <cuda_runtime.h>

// Stochastic-LIF eval-mode scan — FINAL (lock-in of best measured config).
// x: [B=32, T=128, N=8192] f32, o: same shape.
// Recurrence per (b, n): u = 0.5*u + x_t; o = (u > 1); u = o ? 0 : u.
//
// Each thread owns one float4 (4 adjacent n) across all 128 time steps.
// T processed in chunks of 8; the 8 independent LDG.128 are issued via
// asm volatile so ptxas cannot sink them to their uses (true MLP=8 —
// this was the single change that moved DRAM 65% -> 73%).
// Loads and stores both .cs (zero reuse, pure streaming; all L2-policy
// variants measured neutral). 1024 blocks x 64 threads: wave-balanced,
// ~13.8 warps/SM (256-bit/half-thread variant measured as a regression —
// warp count beats access width on sm_103a once width >= 128b).
// Measured: ~37.4 us kernel, 5.8 TB/s DRAM = mixed R/W streaming ceiling.

static constexpr int B = 32;
static constexpr int T = 128;
static constexpr int N = 8192;
static constexpr int NV = N / 4;          // float4 columns per (b, t) row: 2048
static constexpr int CHAINS = B * NV;     // 65536 threads
static constexpr int CH = 8;              // time-chunk (prefetch depth)

__global__ void __launch_bounds__(64)
lif_scan_kernel(const float4* __restrict__ x, float4* __restrict__ o) {
    const int idx = blockIdx.x * blockDim.x + threadIdx.x;   // 0 .. CHAINS-1
    const int b = idx >> 11;          // / NV
    const int n = idx & (NV - 1);     // % NV

    const float4* __restrict__ xp = x + (size_t)b * T * NV + n;
    float4* __restrict__ op       = o + (size_t)b * T * NV + n;

    float ux = 0.f, uy = 0.f, uz = 0.f, uw = 0.f;

    #pragma unroll 1
    for (int t0 = 0; t0 < T; t0 += CH) {
        // Phase 1: 8 independent streaming loads, order-pinned by asm volatile.
        float xr[CH][4];
        #pragma unroll
        for (int i = 0; i < CH; ++i) {
            const float4* p = xp + (size_t)(t0 + i) * NV;
            asm volatile("ld.global.cs.v4.f32 {%0,%1,%2,%3}, [%4];"
                         : "=f"(xr[i][0]), "=f"(xr[i][1]),
                           "=f"(xr[i][2]), "=f"(xr[i][3])
                         : "l"(p));
        }

        // Phase 2: sequential LIF chain; streaming store per step.
        #pragma unroll
        for (int i = 0; i < CH; ++i) {
            ux = fmaf(0.5f, ux, xr[i][0]);
            uy = fmaf(0.5f, uy, xr[i][1]);
            uz = fmaf(0.5f, uz, xr[i][2]);
            uw = fmaf(0.5f, uw, xr[i][3]);

            float ox = (ux > 1.0f) ? 1.0f : 0.0f;
            float oy = (uy > 1.0f) ? 1.0f : 0.0f;
            float oz = (uz > 1.0f) ? 1.0f : 0.0f;
            float ow = (uw > 1.0f) ? 1.0f : 0.0f;

            ux = (ux > 1.0f) ? 0.0f : ux;
            uy = (uy > 1.0f) ? 0.0f : uy;
            uz = (uz > 1.0f) ? 0.0f : uz;
            uw = (uw > 1.0f) ? 0.0f : uw;

            float4* q = op + (size_t)(t0 + i) * NV;
            asm volatile("st.global.cs.v4.f32 [%0], {%1,%2,%3,%4};"
                         :: "l"(q), "f"(ox), "f"(oy), "f"(oz), "f"(ow)
                         : "memory");
        }
    }
}

extern "C" void kernel_launch(void* const* d_in, const int* in_sizes, int n_in,
                              void* d_out, int out_size) {
    const float4* x = (const float4*)d_in[0];
    float4* o = (float4*)d_out;
    (void)in_sizes; (void)n_in; (void)out_size;

    const int threads = 64;
    const int blocks = CHAINS / threads;   // 1024
    lif_scan_kernel<<<blocks, threads>>>(x, o);
}